// round 10
// baseline (speedup 1.0000x reference)
#include <cuda_runtime.h>
#include <math.h>

// Problem constants (shapes fixed by the dataset)
#define NN      50000
#define EEMAX   800000
#define ETMAX   850000   // edges + self loops
#define INC     128

// ---------------- scratch (static __device__; no allocs allowed) ----------------
__device__ float g_h  [NN * 128];   // per-layer projected features (pre-aggregation)
__device__ float g_o1 [NN * 128];   // layer1 output
__device__ float g_o2 [NN * 64];    // layer2 output
__device__ float g_as [NN * 4];     // alpha_src per node per head
__device__ float g_ad [NN * 4];     // alpha_dst per node per head
__device__ int   g_srcA[ETMAX];
__device__ int   g_dstA[ETMAX];
__device__ int   g_ssrc[ETMAX];     // src sorted by dst
__device__ int   g_deg [NN];
__device__ int   g_startA[NN + 1];
__device__ int   g_cursor[NN];
__device__ int   g_bsum[128];
__device__ int   g_is64;

// ---------------- helpers ----------------
__device__ __forceinline__ float leaky(float x) {
    return x >= 0.f ? x : 0.2f * x;
}

template<int H>
__device__ __forceinline__ void loadH(const float* __restrict__ p, float* a) {
    if (H == 4) {
        float4 v = *reinterpret_cast<const float4*>(p);
        a[0] = v.x; a[1] = v.y; a[2] = v.z; a[3] = v.w;
    } else if (H == 2) {
        float2 v = *reinterpret_cast<const float2*>(p);
        a[0] = v.x; a[1] = v.y;
    } else {
        a[0] = p[0];
    }
}

// ---------------- edge preprocessing ----------------
__global__ void k_zero(int n) {
    int i = blockIdx.x * blockDim.x + threadIdx.x;
    if (i < n) { g_deg[i] = 0; g_cursor[i] = 0; }
}

// Detect whether edge_index buffer is int64 (odd 32-bit words ~all zero) or int32.
__global__ void k_detect(const int* __restrict__ p) {
    if (blockIdx.x == 0 && threadIdx.x == 0) {
        int z = 0;
        for (int i = 0; i < 256; i++) if (p[2 * i + 1] == 0) z++;
        g_is64 = (z > 200) ? 1 : 0;
    }
}

__global__ void k_extract(const void* __restrict__ ei, int E, int ET) {
    int i = blockIdx.x * blockDim.x + threadIdx.x;
    if (i >= ET) return;
    int s, d;
    if (i < E) {
        if (g_is64) {
            const long long* p = (const long long*)ei;
            s = (int)p[i]; d = (int)p[(long long)E + i];
        } else {
            const int* p = (const int*)ei;
            s = p[i]; d = p[E + i];
        }
    } else {
        s = d = i - E;   // self loop
    }
    g_srcA[i] = s; g_dstA[i] = d;
    atomicAdd(&g_deg[d], 1);
}

// -------- multi-block exclusive scan: deg -> startA --------
__global__ void k_scan1(int n) {
    __shared__ int wsum[32];
    int t = threadIdx.x;
    int i = blockIdx.x * 1024 + t;
    int v = (i < n) ? g_deg[i] : 0;
    int lane = t & 31, w = t >> 5;
    int x = v;
    #pragma unroll
    for (int d = 1; d < 32; d <<= 1) {
        int y = __shfl_up_sync(0xffffffffu, x, d);
        if (lane >= d) x += y;
    }
    if (lane == 31) wsum[w] = x;
    __syncthreads();
    if (w == 0) {
        int s = wsum[lane];
        #pragma unroll
        for (int d = 1; d < 32; d <<= 1) {
            int y = __shfl_up_sync(0xffffffffu, s, d);
            if (lane >= d) s += y;
        }
        wsum[lane] = s;
    }
    __syncthreads();
    int excl = x - v + (w > 0 ? wsum[w - 1] : 0);
    if (i < n) g_startA[i] = excl;
    if (t == 1023) g_bsum[blockIdx.x] = excl + v;
}

__global__ void k_scan2(int nb, int n) {
    if (threadIdx.x == 0) {
        int run = 0;
        for (int b = 0; b < nb; b++) {
            int v = g_bsum[b];
            g_bsum[b] = run;
            run += v;
        }
        g_startA[n] = run;
    }
}

__global__ void k_scan3(int n) {
    int i = blockIdx.x * 1024 + threadIdx.x;
    if (i < n) g_startA[i] += g_bsum[blockIdx.x];
}

__global__ void k_scatter(int ET) {
    int i = blockIdx.x * blockDim.x + threadIdx.x;
    if (i >= ET) return;
    int d = g_dstA[i];
    int pos = g_startA[d] + atomicAdd(&g_cursor[d], 1);
    g_ssrc[pos] = g_srcA[i];
}

// ------- dense projection GEMM + fused attention coefficients -------
// Hout[n, NOUT] = X[n, K] @ W[K, NOUT];  AS/AD[n, H] = per-head dots with a_src/a_dst.
// Each thread owns TN=NOUT/16 contiguous columns, which lie in exactly one head.
// Per-row head sums reduced over the C/TN lanes sharing that head via shfl_xor.
template<int K, int NOUT, int H, int C>
__global__ void __launch_bounds__(256, 2)
k_gemm(const float* __restrict__ X, const float* __restrict__ W,
       const float* __restrict__ Asrc, const float* __restrict__ Adst,
       float* __restrict__ Hout, float* __restrict__ AS, float* __restrict__ AD,
       int n) {
    constexpr int BM = 128, BK = 32;
    constexpr int TM = 8, TN = NOUT / 16;
    constexpr int LPH = C / TN;        // lanes covering one head (tx-contiguous)
    __shared__ float xs[BK][BM];       // transposed A tile: xs[k][row]
    __shared__ float ws[BK][NOUT];

    int t  = threadIdx.x;
    int tx = t % 16, ty = t / 16;
    int row0 = blockIdx.x * BM;

    float acc[TM][TN];
    #pragma unroll
    for (int i = 0; i < TM; i++)
        #pragma unroll
        for (int j = 0; j < TN; j++) acc[i][j] = 0.f;

    for (int k0 = 0; k0 < K; k0 += BK) {
        #pragma unroll
        for (int i = 0; i < (BM * BK / 4) / 256; i++) {
            int id  = t + i * 256;
            int row = id & (BM - 1);
            int kq  = id >> 7;
            float4 v = make_float4(0.f, 0.f, 0.f, 0.f);
            if (row0 + row < n)
                v = *reinterpret_cast<const float4*>(X + (long long)(row0 + row) * K + k0 + kq * 4);
            xs[kq * 4 + 0][row] = v.x;
            xs[kq * 4 + 1][row] = v.y;
            xs[kq * 4 + 2][row] = v.z;
            xs[kq * 4 + 3][row] = v.w;
        }
        for (int i = t; i < BK * NOUT / 4; i += 256) {
            int kk = i / (NOUT / 4);
            int c4 = i % (NOUT / 4);
            float4 v = *reinterpret_cast<const float4*>(W + (long long)(k0 + kk) * NOUT + c4 * 4);
            *reinterpret_cast<float4*>(&ws[kk][c4 * 4]) = v;
        }
        __syncthreads();

        #pragma unroll
        for (int kk = 0; kk < BK; kk++) {
            float a[TM], b[TN];
            float4 a0 = *reinterpret_cast<const float4*>(&xs[kk][ty * 8]);
            float4 a1 = *reinterpret_cast<const float4*>(&xs[kk][ty * 8 + 4]);
            a[0] = a0.x; a[1] = a0.y; a[2] = a0.z; a[3] = a0.w;
            a[4] = a1.x; a[5] = a1.y; a[6] = a1.z; a[7] = a1.w;
            if (TN == 8) {
                float4 b0 = *reinterpret_cast<const float4*>(&ws[kk][tx * 8]);
                float4 b1 = *reinterpret_cast<const float4*>(&ws[kk][tx * 8 + 4]);
                b[0] = b0.x; b[1] = b0.y; b[2] = b0.z; b[3] = b0.w;
                b[4] = b1.x; b[5] = b1.y; b[6] = b1.z; b[7] = b1.w;
            } else if (TN == 4) {
                float4 b0 = *reinterpret_cast<const float4*>(&ws[kk][tx * 4]);
                b[0] = b0.x; b[1] = b0.y; b[2] = b0.z; b[3] = b0.w;
            } else {
                b[0] = ws[kk][tx];
            }
            #pragma unroll
            for (int i = 0; i < TM; i++)
                #pragma unroll
                for (int j = 0; j < TN; j++) acc[i][j] += a[i] * b[j];
        }
        __syncthreads();
    }

    // store Hout
    #pragma unroll
    for (int i = 0; i < TM; i++) {
        int row = row0 + ty * 8 + i;
        if (row < n) {
            float* orow = Hout + (long long)row * NOUT + tx * TN;
            if (TN == 8) {
                *reinterpret_cast<float4*>(orow)     = make_float4(acc[i][0], acc[i][1], acc[i][2], acc[i][3]);
                *reinterpret_cast<float4*>(orow + 4) = make_float4(acc[i][4], acc[i][5], acc[i][6], acc[i][7]);
            } else if (TN == 4) {
                *reinterpret_cast<float4*>(orow)     = make_float4(acc[i][0], acc[i][1], acc[i][2], acc[i][3]);
            } else {
                orow[0] = acc[i][0];
            }
        }
    }

    // fused alpha: this thread's columns tx*TN.. belong to head (tx*TN)/C
    float asv[TN], adv[TN];
    #pragma unroll
    for (int j = 0; j < TN; j++) {
        asv[j] = Asrc[tx * TN + j];
        adv[j] = Adst[tx * TN + j];
    }
    int head = (tx * TN) / C;
    #pragma unroll
    for (int i = 0; i < TM; i++) {
        float sa = 0.f, sd = 0.f;
        #pragma unroll
        for (int j = 0; j < TN; j++) { sa += acc[i][j] * asv[j]; sd += acc[i][j] * adv[j]; }
        #pragma unroll
        for (int off = 1; off < LPH; off <<= 1) {
            sa += __shfl_xor_sync(0xffffffffu, sa, off);
            sd += __shfl_xor_sync(0xffffffffu, sd, off);
        }
        int row = row0 + ty * 8 + i;
        if ((tx % LPH) == 0 && row < n) {
            AS[row * H + head] = sa;
            AD[row * H + head] = sd;
        }
    }
}

// ---------------- warp-per-node ONE-PASS online softmax + aggregation ----------------
// NG = 32/(HC/4) gather groups per warp; group g handles chunk edges j = g, g+NG, ...
// Running rescale sc is warp-uniform, so per-group partial accs sum correctly at the end.
template<int H, int C, bool RELU>
__global__ void k_agg(const float* __restrict__ Hf, const float* __restrict__ AS,
                      const float* __restrict__ AD, const int* __restrict__ startA,
                      const int* __restrict__ ssrc, const float* __restrict__ bias,
                      float* __restrict__ out, int n) {
    constexpr int HC  = H * C;
    constexpr int GL  = HC / 4;                  // lanes per gather group (float4 each)
    constexpr int NG  = 32 / GL;                 // gather groups per warp
    constexpr int WPB = 8;                       // warps per block
    int warp = threadIdx.x >> 5, lane = threadIdx.x & 31;
    int nd = blockIdx.x * WPB + warp;
    if (nd >= n) return;

    __shared__ float s_w[WPB][H * 33];           // [h*33 + lane]: conflict-free
    __shared__ int   s_s[WPB][32];

    int beg = startA[nd], end = startA[nd + 1];

    float ad[H];
    loadH<H>(AD + nd * H, ad);

    int grp = lane / GL;                         // gather group
    int q   = lane % GL;                         // channel quad within row
    int myhead = (q * 4) / C;                    // per-lane constant
    float m[H], s[H], acc[4];
    #pragma unroll
    for (int h = 0; h < H; h++) { m[h] = -INFINITY; s[h] = 0.f; }
    #pragma unroll
    for (int v = 0; v < 4; v++) acc[v] = 0.f;

    for (int cbeg = beg; cbeg < end; cbeg += 32) {
        int cl = end - cbeg; if (cl > 32) cl = 32;

        float l[H];
        int src = 0;
        if (lane < cl) {
            src = ssrc[cbeg + lane];
            float as[H];
            loadH<H>(AS + src * H, as);
            #pragma unroll
            for (int h = 0; h < H; h++) l[h] = leaky(as[h] + ad[h]);
        } else {
            #pragma unroll
            for (int h = 0; h < H; h++) l[h] = -INFINITY;
        }

        // chunk max (butterfly)
        float cm[H];
        #pragma unroll
        for (int h = 0; h < H; h++) cm[h] = l[h];
        #pragma unroll
        for (int off = 16; off > 0; off >>= 1)
            #pragma unroll
            for (int h = 0; h < H; h++)
                cm[h] = fmaxf(cm[h], __shfl_xor_sync(0xffffffffu, cm[h], off));

        // merge with running max; rescale factors (m=-inf on first chunk -> exp(-inf)=0)
        float nm[H], sc[H], w[H], cs[H];
        #pragma unroll
        for (int h = 0; h < H; h++) {
            nm[h] = fmaxf(m[h], cm[h]);          // finite: cl >= 1
            sc[h] = __expf(m[h] - nm[h]);
            w[h]  = __expf(l[h] - nm[h]);        // lane >= cl: exp(-inf)=0
            cs[h] = w[h];
            m[h]  = nm[h];
        }
        // chunk exp-sum (butterfly)
        #pragma unroll
        for (int off = 16; off > 0; off >>= 1)
            #pragma unroll
            for (int h = 0; h < H; h++)
                cs[h] += __shfl_xor_sync(0xffffffffu, cs[h], off);
        #pragma unroll
        for (int h = 0; h < H; h++) s[h] = s[h] * sc[h] + cs[h];

        if (lane < cl) {
            s_s[warp][lane] = src;
            #pragma unroll
            for (int h = 0; h < H; h++) s_w[warp][h * 33 + lane] = w[h];
        }
        __syncwarp();

        {
            float rs = sc[myhead];
            #pragma unroll
            for (int v = 0; v < 4; v++) acc[v] *= rs;
            const float* base = Hf + (long long)q * 4;
            #pragma unroll 4
            for (int j = grp; j < cl; j += NG) {
                float  wj  = s_w[warp][myhead * 33 + j];
                float4 v   = *reinterpret_cast<const float4*>(base + (long long)s_s[warp][j] * HC);
                acc[0] += wj * v.x; acc[1] += wj * v.y;
                acc[2] += wj * v.z; acc[3] += wj * v.w;
            }
        }
        __syncwarp();
    }

    // sum partial accumulators across gather groups (xor on high lane bits)
    #pragma unroll
    for (int off = GL; off < 32; off <<= 1) {
        #pragma unroll
        for (int v = 0; v < 4; v++)
            acc[v] += __shfl_xor_sync(0xffffffffu, acc[v], off);
    }

    if (lane < GL) {
        float inv = 1.f / (s[myhead] + 1e-16f);
        float4 bv = *reinterpret_cast<const float4*>(bias + lane * 4);
        float4 o;
        o.x = acc[0] * inv + bv.x;
        o.y = acc[1] * inv + bv.y;
        o.z = acc[2] * inv + bv.z;
        o.w = acc[3] * inv + bv.w;
        if (RELU) {
            o.x = fmaxf(o.x, 0.f); o.y = fmaxf(o.y, 0.f);
            o.z = fmaxf(o.z, 0.f); o.w = fmaxf(o.w, 0.f);
        }
        *reinterpret_cast<float4*>(out + (long long)nd * HC + lane * 4) = o;
    }
}

// ---------------- launcher ----------------
extern "C" void kernel_launch(void* const* d_in, const int* in_sizes, int n_in,
                              void* d_out, int out_size) {
    const float* x     = (const float*)d_in[0];
    const void*  ei    = d_in[1];
    const float* W1    = (const float*)d_in[2];
    const float* asr1  = (const float*)d_in[3];
    const float* ads1  = (const float*)d_in[4];
    const float* b1    = (const float*)d_in[5];
    const float* W2    = (const float*)d_in[6];
    const float* asr2  = (const float*)d_in[7];
    const float* ads2  = (const float*)d_in[8];
    const float* b2    = (const float*)d_in[9];
    const float* W3    = (const float*)d_in[10];
    const float* asr3  = (const float*)d_in[11];
    const float* ads3  = (const float*)d_in[12];
    const float* b3    = (const float*)d_in[13];

    int N  = in_sizes[0] / INC;
    int E  = in_sizes[1] / 2;
    int ET = E + N;

    void* p;
    cudaGetSymbolAddress(&p, g_h);      float* d_h   = (float*)p;
    cudaGetSymbolAddress(&p, g_o1);     float* d_o1  = (float*)p;
    cudaGetSymbolAddress(&p, g_o2);     float* d_o2  = (float*)p;
    cudaGetSymbolAddress(&p, g_as);     float* d_as  = (float*)p;
    cudaGetSymbolAddress(&p, g_ad);     float* d_ad  = (float*)p;
    cudaGetSymbolAddress(&p, g_startA); int*   d_st  = (int*)p;
    cudaGetSymbolAddress(&p, g_ssrc);   int*   d_ss  = (int*)p;

    // edge preprocessing: counting sort by destination
    int nb = (N + 1023) / 1024;
    k_zero   <<<(N  + 255) / 256, 256>>>(N);
    k_detect <<<1, 32>>>((const int*)ei);
    k_extract<<<(ET + 255) / 256, 256>>>(ei, E, ET);
    k_scan1  <<<nb, 1024>>>(N);
    k_scan2  <<<1, 32>>>(nb, N);
    k_scan3  <<<nb, 1024>>>(N);
    k_scatter<<<(ET + 255) / 256, 256>>>(ET);

    int gB = (N + 127) / 128;
    int gA = (N + 7) / 8;        // 8 warps (nodes) per 256-thread block

    // layer 1: 128 -> 4 heads x 32, concat, relu
    k_gemm<128, 128, 4, 32><<<gB, 256>>>(x, W1, asr1, ads1, d_h, d_as, d_ad, N);
    k_agg<4, 32, true><<<gA, 256>>>(d_h, d_as, d_ad, d_st, d_ss, b1, d_o1, N);

    // layer 2: 128 -> 2 heads x 32, concat, relu
    k_gemm<128, 64, 2, 32><<<gB, 256>>>(d_o1, W2, asr2, ads2, d_h, d_as, d_ad, N);
    k_agg<2, 32, true><<<gA, 256>>>(d_h, d_as, d_ad, d_st, d_ss, b2, d_o2, N);

    // layer 3: 64 -> 1 head x 16, mean (identity for 1 head), no relu
    k_gemm<64, 16, 1, 16><<<gB, 256>>>(d_o2, W3, asr3, ads3, d_h, d_as, d_ad, N);
    k_agg<1, 16, false><<<gA, 256>>>(d_h, d_as, d_ad, d_st, d_ss, b3, (float*)d_out, N);
}

// round 12
// speedup vs baseline: 1.4604x; 1.4604x over previous
#include <cuda_runtime.h>
#include <math.h>

// Problem constants (shapes fixed by the dataset)
#define NN      50000
#define EEMAX   800000
#define ETMAX   850000   // edges + self loops
#define INC     128

// ---------------- scratch (static __device__; no allocs allowed) ----------------
__device__ float g_h  [NN * 128];   // per-layer projected features (pre-aggregation)
__device__ float g_o1 [NN * 128];   // layer1 output
__device__ float g_o2 [NN * 64];    // layer2 output
__device__ float g_as [NN * 4];     // alpha_src per node per head
__device__ float g_ad [NN * 4];     // alpha_dst per node per head
__device__ int   g_srcA[ETMAX];
__device__ int   g_dstA[ETMAX];
__device__ int   g_ssrc[ETMAX];     // src sorted by dst
__device__ int   g_deg [NN];
__device__ int   g_startA[NN + 1];
__device__ int   g_cursor[NN];
__device__ int   g_bsum[128];
__device__ int   g_is64;

// ---------------- helpers ----------------
__device__ __forceinline__ float leaky(float x) {
    return x >= 0.f ? x : 0.2f * x;
}

template<int H>
__device__ __forceinline__ void loadH(const float* __restrict__ p, float* a) {
    if (H == 4) {
        float4 v = *reinterpret_cast<const float4*>(p);
        a[0] = v.x; a[1] = v.y; a[2] = v.z; a[3] = v.w;
    } else if (H == 2) {
        float2 v = *reinterpret_cast<const float2*>(p);
        a[0] = v.x; a[1] = v.y;
    } else {
        a[0] = p[0];
    }
}

// ---------------- edge preprocessing ----------------
__global__ void k_zero(int n) {
    int i = blockIdx.x * blockDim.x + threadIdx.x;
    if (i < n) { g_deg[i] = 0; g_cursor[i] = 0; }
}

// Detect whether edge_index buffer is int64 (odd 32-bit words ~all zero) or int32.
__global__ void k_detect(const int* __restrict__ p) {
    if (blockIdx.x == 0 && threadIdx.x == 0) {
        int z = 0;
        for (int i = 0; i < 256; i++) if (p[2 * i + 1] == 0) z++;
        g_is64 = (z > 200) ? 1 : 0;
    }
}

__global__ void k_extract(const void* __restrict__ ei, int E, int ET) {
    int i = blockIdx.x * blockDim.x + threadIdx.x;
    if (i >= ET) return;
    int s, d;
    if (i < E) {
        if (g_is64) {
            const long long* p = (const long long*)ei;
            s = (int)p[i]; d = (int)p[(long long)E + i];
        } else {
            const int* p = (const int*)ei;
            s = p[i]; d = p[E + i];
        }
    } else {
        s = d = i - E;   // self loop
    }
    g_srcA[i] = s; g_dstA[i] = d;
    atomicAdd(&g_deg[d], 1);
}

// -------- multi-block exclusive scan: deg -> startA --------
__global__ void k_scan1(int n) {
    __shared__ int wsum[32];
    int t = threadIdx.x;
    int i = blockIdx.x * 1024 + t;
    int v = (i < n) ? g_deg[i] : 0;
    int lane = t & 31, w = t >> 5;
    int x = v;
    #pragma unroll
    for (int d = 1; d < 32; d <<= 1) {
        int y = __shfl_up_sync(0xffffffffu, x, d);
        if (lane >= d) x += y;
    }
    if (lane == 31) wsum[w] = x;
    __syncthreads();
    if (w == 0) {
        int s = wsum[lane];
        #pragma unroll
        for (int d = 1; d < 32; d <<= 1) {
            int y = __shfl_up_sync(0xffffffffu, s, d);
            if (lane >= d) s += y;
        }
        wsum[lane] = s;
    }
    __syncthreads();
    int excl = x - v + (w > 0 ? wsum[w - 1] : 0);
    if (i < n) g_startA[i] = excl;
    if (t == 1023) g_bsum[blockIdx.x] = excl + v;
}

__global__ void k_scan2(int nb, int n) {
    if (threadIdx.x == 0) {
        int run = 0;
        for (int b = 0; b < nb; b++) {
            int v = g_bsum[b];
            g_bsum[b] = run;
            run += v;
        }
        g_startA[n] = run;
    }
}

__global__ void k_scan3(int n) {
    int i = blockIdx.x * 1024 + threadIdx.x;
    if (i < n) g_startA[i] += g_bsum[blockIdx.x];
}

__global__ void k_scatter(int ET) {
    int i = blockIdx.x * blockDim.x + threadIdx.x;
    if (i >= ET) return;
    int d = g_dstA[i];
    int pos = g_startA[d] + atomicAdd(&g_cursor[d], 1);
    g_ssrc[pos] = g_srcA[i];
}

// ---------------- dense projection GEMM: Hout[n, NOUT] = X[n, K] @ W[K, NOUT] ----------------
// BM=128, BK=32, BN=NOUT; 256 threads; per-thread 8 x (NOUT/16) with float4 smem traffic.
// NOTE: no epilogue fusion here — the 64-reg accumulator file has zero register
// headroom under __launch_bounds__(256,2); adding epilogue state spills (R7 regression).
template<int K, int NOUT>
__global__ void __launch_bounds__(256, 2)
k_gemm(const float* __restrict__ X, const float* __restrict__ W,
       float* __restrict__ Hout, int n) {
    constexpr int BM = 128, BK = 32;
    constexpr int TM = 8, TN = NOUT / 16;
    __shared__ float xs[BK][BM];       // transposed A tile: xs[k][row]
    __shared__ float ws[BK][NOUT];

    int t  = threadIdx.x;
    int tx = t % 16, ty = t / 16;
    int row0 = blockIdx.x * BM;

    float acc[TM][TN];
    #pragma unroll
    for (int i = 0; i < TM; i++)
        #pragma unroll
        for (int j = 0; j < TN; j++) acc[i][j] = 0.f;

    for (int k0 = 0; k0 < K; k0 += BK) {
        #pragma unroll
        for (int i = 0; i < (BM * BK / 4) / 256; i++) {
            int id  = t + i * 256;
            int row = id & (BM - 1);
            int kq  = id >> 7;
            float4 v = make_float4(0.f, 0.f, 0.f, 0.f);
            if (row0 + row < n)
                v = *reinterpret_cast<const float4*>(X + (long long)(row0 + row) * K + k0 + kq * 4);
            xs[kq * 4 + 0][row] = v.x;
            xs[kq * 4 + 1][row] = v.y;
            xs[kq * 4 + 2][row] = v.z;
            xs[kq * 4 + 3][row] = v.w;
        }
        for (int i = t; i < BK * NOUT / 4; i += 256) {
            int kk = i / (NOUT / 4);
            int c4 = i % (NOUT / 4);
            float4 v = *reinterpret_cast<const float4*>(W + (long long)(k0 + kk) * NOUT + c4 * 4);
            *reinterpret_cast<float4*>(&ws[kk][c4 * 4]) = v;
        }
        __syncthreads();

        #pragma unroll
        for (int kk = 0; kk < BK; kk++) {
            float a[TM], b[TN];
            float4 a0 = *reinterpret_cast<const float4*>(&xs[kk][ty * 8]);
            float4 a1 = *reinterpret_cast<const float4*>(&xs[kk][ty * 8 + 4]);
            a[0] = a0.x; a[1] = a0.y; a[2] = a0.z; a[3] = a0.w;
            a[4] = a1.x; a[5] = a1.y; a[6] = a1.z; a[7] = a1.w;
            if (TN == 8) {
                float4 b0 = *reinterpret_cast<const float4*>(&ws[kk][tx * 8]);
                float4 b1 = *reinterpret_cast<const float4*>(&ws[kk][tx * 8 + 4]);
                b[0] = b0.x; b[1] = b0.y; b[2] = b0.z; b[3] = b0.w;
                b[4] = b1.x; b[5] = b1.y; b[6] = b1.z; b[7] = b1.w;
            } else if (TN == 4) {
                float4 b0 = *reinterpret_cast<const float4*>(&ws[kk][tx * 4]);
                b[0] = b0.x; b[1] = b0.y; b[2] = b0.z; b[3] = b0.w;
            } else {
                b[0] = ws[kk][tx];
            }
            #pragma unroll
            for (int i = 0; i < TM; i++)
                #pragma unroll
                for (int j = 0; j < TN; j++) acc[i][j] += a[i] * b[j];
        }
        __syncthreads();
    }

    #pragma unroll
    for (int i = 0; i < TM; i++) {
        int row = row0 + ty * 8 + i;
        if (row < n) {
            float* orow = Hout + (long long)row * NOUT + tx * TN;
            if (TN == 8) {
                *reinterpret_cast<float4*>(orow)     = make_float4(acc[i][0], acc[i][1], acc[i][2], acc[i][3]);
                *reinterpret_cast<float4*>(orow + 4) = make_float4(acc[i][4], acc[i][5], acc[i][6], acc[i][7]);
            } else if (TN == 4) {
                *reinterpret_cast<float4*>(orow)     = make_float4(acc[i][0], acc[i][1], acc[i][2], acc[i][3]);
            } else {
                orow[0] = acc[i][0];
            }
        }
    }
}

// ---------------- per-node attention coefficients (float4, fully unrolled) ----------------
template<int H, int C>
__global__ void k_alpha(const float* __restrict__ Hf, const float* __restrict__ Asrc,
                        const float* __restrict__ Adst, float* __restrict__ AS,
                        float* __restrict__ AD, int n) {
    constexpr int HC = H * C;
    int i = blockIdx.x * blockDim.x + threadIdx.x;
    if (i >= n) return;
    float sa[H], sd[H];
    #pragma unroll
    for (int h = 0; h < H; h++) { sa[h] = 0.f; sd[h] = 0.f; }
    const float4* row = reinterpret_cast<const float4*>(Hf + (long long)i * HC);
    #pragma unroll
    for (int q = 0; q < HC / 4; q++) {
        float4 v = row[q];
        int h = (q * 4) / C;
        float4 asv = reinterpret_cast<const float4*>(Asrc)[q];
        float4 adv = reinterpret_cast<const float4*>(Adst)[q];
        sa[h] += v.x * asv.x + v.y * asv.y + v.z * asv.z + v.w * asv.w;
        sd[h] += v.x * adv.x + v.y * adv.y + v.z * adv.z + v.w * adv.w;
    }
    #pragma unroll
    for (int h = 0; h < H; h++) {
        AS[i * H + h] = sa[h];
        AD[i * H + h] = sd[h];
    }
}

// ---------------- warp-per-node ONE-PASS online softmax + aggregation ----------------
// NG = 32/(HC/4) gather groups per warp; group g handles chunk edges j = g, g+NG, ...
// Running rescale sc is warp-uniform, so per-group partial accs sum correctly at the end.
template<int H, int C, bool RELU>
__global__ void k_agg(const float* __restrict__ Hf, const float* __restrict__ AS,
                      const float* __restrict__ AD, const int* __restrict__ startA,
                      const int* __restrict__ ssrc, const float* __restrict__ bias,
                      float* __restrict__ out, int n) {
    constexpr int HC  = H * C;
    constexpr int GL  = HC / 4;                  // lanes per gather group (float4 each)
    constexpr int NG  = 32 / GL;                 // gather groups per warp
    constexpr int WPB = 8;                       // warps per block
    int warp = threadIdx.x >> 5, lane = threadIdx.x & 31;
    int nd = blockIdx.x * WPB + warp;
    if (nd >= n) return;

    __shared__ float s_w[WPB][H * 33];           // [h*33 + lane]: conflict-free
    __shared__ int   s_s[WPB][32];

    int beg = startA[nd], end = startA[nd + 1];

    float ad[H];
    loadH<H>(AD + nd * H, ad);

    int grp = lane / GL;                         // gather group
    int q   = lane % GL;                         // channel quad within row
    int myhead = (q * 4) / C;                    // per-lane constant
    float m[H], s[H], acc[4];
    #pragma unroll
    for (int h = 0; h < H; h++) { m[h] = -INFINITY; s[h] = 0.f; }
    #pragma unroll
    for (int v = 0; v < 4; v++) acc[v] = 0.f;

    for (int cbeg = beg; cbeg < end; cbeg += 32) {
        int cl = end - cbeg; if (cl > 32) cl = 32;

        float l[H];
        int src = 0;
        if (lane < cl) {
            src = ssrc[cbeg + lane];
            float as[H];
            loadH<H>(AS + src * H, as);
            #pragma unroll
            for (int h = 0; h < H; h++) l[h] = leaky(as[h] + ad[h]);
        } else {
            #pragma unroll
            for (int h = 0; h < H; h++) l[h] = -INFINITY;
        }

        // chunk max (butterfly)
        float cm[H];
        #pragma unroll
        for (int h = 0; h < H; h++) cm[h] = l[h];
        #pragma unroll
        for (int off = 16; off > 0; off >>= 1)
            #pragma unroll
            for (int h = 0; h < H; h++)
                cm[h] = fmaxf(cm[h], __shfl_xor_sync(0xffffffffu, cm[h], off));

        // merge with running max; rescale factors (m=-inf on first chunk -> exp(-inf)=0)
        float nm[H], sc[H], w[H], cs[H];
        #pragma unroll
        for (int h = 0; h < H; h++) {
            nm[h] = fmaxf(m[h], cm[h]);          // finite: cl >= 1
            sc[h] = __expf(m[h] - nm[h]);
            w[h]  = __expf(l[h] - nm[h]);        // lane >= cl: exp(-inf)=0
            cs[h] = w[h];
            m[h]  = nm[h];
        }
        // chunk exp-sum (butterfly)
        #pragma unroll
        for (int off = 16; off > 0; off >>= 1)
            #pragma unroll
            for (int h = 0; h < H; h++)
                cs[h] += __shfl_xor_sync(0xffffffffu, cs[h], off);
        #pragma unroll
        for (int h = 0; h < H; h++) s[h] = s[h] * sc[h] + cs[h];

        if (lane < cl) {
            s_s[warp][lane] = src;
            #pragma unroll
            for (int h = 0; h < H; h++) s_w[warp][h * 33 + lane] = w[h];
        }
        __syncwarp();

        {
            float rs = sc[myhead];
            #pragma unroll
            for (int v = 0; v < 4; v++) acc[v] *= rs;
            const float* base = Hf + (long long)q * 4;
            #pragma unroll 4
            for (int j = grp; j < cl; j += NG) {
                float  wj  = s_w[warp][myhead * 33 + j];
                float4 v   = *reinterpret_cast<const float4*>(base + (long long)s_s[warp][j] * HC);
                acc[0] += wj * v.x; acc[1] += wj * v.y;
                acc[2] += wj * v.z; acc[3] += wj * v.w;
            }
        }
        __syncwarp();
    }

    // sum partial accumulators across gather groups (xor on high lane bits; no-op when NG==1)
    #pragma unroll
    for (int off = GL; off < 32; off <<= 1) {
        #pragma unroll
        for (int v = 0; v < 4; v++)
            acc[v] += __shfl_xor_sync(0xffffffffu, acc[v], off);
    }

    if (lane < GL) {
        float inv = 1.f / (s[myhead] + 1e-16f);
        float4 bv = *reinterpret_cast<const float4*>(bias + lane * 4);
        float4 o;
        o.x = acc[0] * inv + bv.x;
        o.y = acc[1] * inv + bv.y;
        o.z = acc[2] * inv + bv.z;
        o.w = acc[3] * inv + bv.w;
        if (RELU) {
            o.x = fmaxf(o.x, 0.f); o.y = fmaxf(o.y, 0.f);
            o.z = fmaxf(o.z, 0.f); o.w = fmaxf(o.w, 0.f);
        }
        *reinterpret_cast<float4*>(out + (long long)nd * HC + lane * 4) = o;
    }
}

// ---------------- launcher ----------------
extern "C" void kernel_launch(void* const* d_in, const int* in_sizes, int n_in,
                              void* d_out, int out_size) {
    const float* x     = (const float*)d_in[0];
    const void*  ei    = d_in[1];
    const float* W1    = (const float*)d_in[2];
    const float* asr1  = (const float*)d_in[3];
    const float* ads1  = (const float*)d_in[4];
    const float* b1    = (const float*)d_in[5];
    const float* W2    = (const float*)d_in[6];
    const float* asr2  = (const float*)d_in[7];
    const float* ads2  = (const float*)d_in[8];
    const float* b2    = (const float*)d_in[9];
    const float* W3    = (const float*)d_in[10];
    const float* asr3  = (const float*)d_in[11];
    const float* ads3  = (const float*)d_in[12];
    const float* b3    = (const float*)d_in[13];

    int N  = in_sizes[0] / INC;
    int E  = in_sizes[1] / 2;
    int ET = E + N;

    void* p;
    cudaGetSymbolAddress(&p, g_h);      float* d_h   = (float*)p;
    cudaGetSymbolAddress(&p, g_o1);     float* d_o1  = (float*)p;
    cudaGetSymbolAddress(&p, g_o2);     float* d_o2  = (float*)p;
    cudaGetSymbolAddress(&p, g_as);     float* d_as  = (float*)p;
    cudaGetSymbolAddress(&p, g_ad);     float* d_ad  = (float*)p;
    cudaGetSymbolAddress(&p, g_startA); int*   d_st  = (int*)p;
    cudaGetSymbolAddress(&p, g_ssrc);   int*   d_ss  = (int*)p;

    // edge preprocessing: counting sort by destination
    int nb = (N + 1023) / 1024;
    k_zero   <<<(N  + 255) / 256, 256>>>(N);
    k_detect <<<1, 32>>>((const int*)ei);
    k_extract<<<(ET + 255) / 256, 256>>>(ei, E, ET);
    k_scan1  <<<nb, 1024>>>(N);
    k_scan2  <<<1, 32>>>(nb, N);
    k_scan3  <<<nb, 1024>>>(N);
    k_scatter<<<(ET + 255) / 256, 256>>>(ET);

    int gB = (N + 127) / 128;
    int gA = (N + 7) / 8;        // 8 warps (nodes) per 256-thread block

    // layer 1: 128 -> 4 heads x 32, concat, relu
    k_gemm<128, 128><<<gB, 256>>>(x, W1, d_h, N);
    k_alpha<4, 32><<<(N + 127) / 128, 128>>>(d_h, asr1, ads1, d_as, d_ad, N);
    k_agg<4, 32, true><<<gA, 256>>>(d_h, d_as, d_ad, d_st, d_ss, b1, d_o1, N);

    // layer 2: 128 -> 2 heads x 32, concat, relu
    k_gemm<128, 64><<<gB, 256>>>(d_o1, W2, d_h, N);
    k_alpha<2, 32><<<(N + 127) / 128, 128>>>(d_h, asr2, ads2, d_as, d_ad, N);
    k_agg<2, 32, true><<<gA, 256>>>(d_h, d_as, d_ad, d_st, d_ss, b2, d_o2, N);

    // layer 3: 64 -> 1 head x 16, mean (identity for 1 head), no relu
    k_gemm<64, 16><<<gB, 256>>>(d_o2, W3, d_h, N);
    k_alpha<1, 16><<<(N + 127) / 128, 128>>>(d_h, asr3, ads3, d_as, d_ad, N);
    k_agg<1, 16, false><<<gA, 256>>>(d_h, d_as, d_ad, d_st, d_ss, b3, (float*)d_out, N);
}

// round 13
// speedup vs baseline: 1.5860x; 1.0860x over previous
#include <cuda_runtime.h>
#include <math.h>

// Problem constants (shapes fixed by the dataset)
#define NN      50000
#define EEMAX   800000
#define ETMAX   850000   // edges + self loops
#define INC     128

// ---------------- scratch (static __device__; no allocs allowed) ----------------
__device__ float g_h  [NN * 128];   // per-layer projected features (pre-aggregation)
__device__ float g_o1 [NN * 128];   // layer1 output
__device__ float g_o2 [NN * 64];    // layer2 output
__device__ float g_as [NN * 4];     // alpha_src per node per head
__device__ float g_ad [NN * 4];     // alpha_dst per node per head
__device__ int   g_srcA[ETMAX];
__device__ int   g_dstA[ETMAX];
__device__ int   g_ssrc[ETMAX];     // src sorted by dst
__device__ int   g_deg [NN];
__device__ int   g_startA[NN + 1];
__device__ int   g_cursor[NN];
__device__ int   g_bsum[128];
__device__ int   g_is64;

// ---------------- helpers ----------------
__device__ __forceinline__ float leaky(float x) {
    return x >= 0.f ? x : 0.2f * x;
}

template<int H>
__device__ __forceinline__ void loadH(const float* __restrict__ p, float* a) {
    if (H == 4) {
        float4 v = *reinterpret_cast<const float4*>(p);
        a[0] = v.x; a[1] = v.y; a[2] = v.z; a[3] = v.w;
    } else if (H == 2) {
        float2 v = *reinterpret_cast<const float2*>(p);
        a[0] = v.x; a[1] = v.y;
    } else {
        a[0] = p[0];
    }
}

// ---------------- edge preprocessing ----------------
__global__ void k_zero(int n) {
    int i = blockIdx.x * blockDim.x + threadIdx.x;
    if (i < n) { g_deg[i] = 0; g_cursor[i] = 0; }
}

// Detect whether edge_index buffer is int64 (odd 32-bit words ~all zero) or int32.
__global__ void k_detect(const int* __restrict__ p) {
    if (blockIdx.x == 0 && threadIdx.x == 0) {
        int z = 0;
        for (int i = 0; i < 256; i++) if (p[2 * i + 1] == 0) z++;
        g_is64 = (z > 200) ? 1 : 0;
    }
}

__global__ void k_extract(const void* __restrict__ ei, int E, int ET) {
    int i = blockIdx.x * blockDim.x + threadIdx.x;
    if (i >= ET) return;
    int s, d;
    if (i < E) {
        if (g_is64) {
            const long long* p = (const long long*)ei;
            s = (int)p[i]; d = (int)p[(long long)E + i];
        } else {
            const int* p = (const int*)ei;
            s = p[i]; d = p[E + i];
        }
    } else {
        s = d = i - E;   // self loop
    }
    g_srcA[i] = s; g_dstA[i] = d;
    atomicAdd(&g_deg[d], 1);
}

// -------- multi-block exclusive scan: deg -> startA --------
__global__ void k_scan1(int n) {
    __shared__ int wsum[32];
    int t = threadIdx.x;
    int i = blockIdx.x * 1024 + t;
    int v = (i < n) ? g_deg[i] : 0;
    int lane = t & 31, w = t >> 5;
    int x = v;
    #pragma unroll
    for (int d = 1; d < 32; d <<= 1) {
        int y = __shfl_up_sync(0xffffffffu, x, d);
        if (lane >= d) x += y;
    }
    if (lane == 31) wsum[w] = x;
    __syncthreads();
    if (w == 0) {
        int s = wsum[lane];
        #pragma unroll
        for (int d = 1; d < 32; d <<= 1) {
            int y = __shfl_up_sync(0xffffffffu, s, d);
            if (lane >= d) s += y;
        }
        wsum[lane] = s;
    }
    __syncthreads();
    int excl = x - v + (w > 0 ? wsum[w - 1] : 0);
    if (i < n) g_startA[i] = excl;
    if (t == 1023) g_bsum[blockIdx.x] = excl + v;
}

__global__ void k_scan2(int nb, int n) {
    if (threadIdx.x == 0) {
        int run = 0;
        for (int b = 0; b < nb; b++) {
            int v = g_bsum[b];
            g_bsum[b] = run;
            run += v;
        }
        g_startA[n] = run;
    }
}

__global__ void k_scan3(int n) {
    int i = blockIdx.x * 1024 + threadIdx.x;
    if (i < n) g_startA[i] += g_bsum[blockIdx.x];
}

__global__ void k_scatter(int ET) {
    int i = blockIdx.x * blockDim.x + threadIdx.x;
    if (i >= ET) return;
    int d = g_dstA[i];
    int pos = g_startA[d] + atomicAdd(&g_cursor[d], 1);
    g_ssrc[pos] = g_srcA[i];
}

// ---------------- dense projection GEMM: Hout[n, NOUT] = X[n, K] @ W[K, NOUT] ----------------
// BM=128, BK=32, BN=NOUT; 256 threads; per-thread 8 x (NOUT/16) with float4 smem traffic.
// NOTE: no epilogue fusion here — the 64-reg accumulator file has zero register
// headroom under __launch_bounds__(256,2); adding epilogue state spills (R7 regression).
template<int K, int NOUT>
__global__ void __launch_bounds__(256, 2)
k_gemm(const float* __restrict__ X, const float* __restrict__ W,
       float* __restrict__ Hout, int n) {
    constexpr int BM = 128, BK = 32;
    constexpr int TM = 8, TN = NOUT / 16;
    __shared__ float xs[BK][BM];       // transposed A tile: xs[k][row]
    __shared__ float ws[BK][NOUT];

    int t  = threadIdx.x;
    int tx = t % 16, ty = t / 16;
    int row0 = blockIdx.x * BM;

    float acc[TM][TN];
    #pragma unroll
    for (int i = 0; i < TM; i++)
        #pragma unroll
        for (int j = 0; j < TN; j++) acc[i][j] = 0.f;

    for (int k0 = 0; k0 < K; k0 += BK) {
        #pragma unroll
        for (int i = 0; i < (BM * BK / 4) / 256; i++) {
            int id  = t + i * 256;
            int row = id & (BM - 1);
            int kq  = id >> 7;
            float4 v = make_float4(0.f, 0.f, 0.f, 0.f);
            if (row0 + row < n)
                v = *reinterpret_cast<const float4*>(X + (long long)(row0 + row) * K + k0 + kq * 4);
            xs[kq * 4 + 0][row] = v.x;
            xs[kq * 4 + 1][row] = v.y;
            xs[kq * 4 + 2][row] = v.z;
            xs[kq * 4 + 3][row] = v.w;
        }
        for (int i = t; i < BK * NOUT / 4; i += 256) {
            int kk = i / (NOUT / 4);
            int c4 = i % (NOUT / 4);
            float4 v = *reinterpret_cast<const float4*>(W + (long long)(k0 + kk) * NOUT + c4 * 4);
            *reinterpret_cast<float4*>(&ws[kk][c4 * 4]) = v;
        }
        __syncthreads();

        #pragma unroll
        for (int kk = 0; kk < BK; kk++) {
            float a[TM], b[TN];
            float4 a0 = *reinterpret_cast<const float4*>(&xs[kk][ty * 8]);
            float4 a1 = *reinterpret_cast<const float4*>(&xs[kk][ty * 8 + 4]);
            a[0] = a0.x; a[1] = a0.y; a[2] = a0.z; a[3] = a0.w;
            a[4] = a1.x; a[5] = a1.y; a[6] = a1.z; a[7] = a1.w;
            if (TN == 8) {
                float4 b0 = *reinterpret_cast<const float4*>(&ws[kk][tx * 8]);
                float4 b1 = *reinterpret_cast<const float4*>(&ws[kk][tx * 8 + 4]);
                b[0] = b0.x; b[1] = b0.y; b[2] = b0.z; b[3] = b0.w;
                b[4] = b1.x; b[5] = b1.y; b[6] = b1.z; b[7] = b1.w;
            } else if (TN == 4) {
                float4 b0 = *reinterpret_cast<const float4*>(&ws[kk][tx * 4]);
                b[0] = b0.x; b[1] = b0.y; b[2] = b0.z; b[3] = b0.w;
            } else {
                b[0] = ws[kk][tx];
            }
            #pragma unroll
            for (int i = 0; i < TM; i++)
                #pragma unroll
                for (int j = 0; j < TN; j++) acc[i][j] += a[i] * b[j];
        }
        __syncthreads();
    }

    #pragma unroll
    for (int i = 0; i < TM; i++) {
        int row = row0 + ty * 8 + i;
        if (row < n) {
            float* orow = Hout + (long long)row * NOUT + tx * TN;
            if (TN == 8) {
                *reinterpret_cast<float4*>(orow)     = make_float4(acc[i][0], acc[i][1], acc[i][2], acc[i][3]);
                *reinterpret_cast<float4*>(orow + 4) = make_float4(acc[i][4], acc[i][5], acc[i][6], acc[i][7]);
            } else if (TN == 4) {
                *reinterpret_cast<float4*>(orow)     = make_float4(acc[i][0], acc[i][1], acc[i][2], acc[i][3]);
            } else {
                orow[0] = acc[i][0];
            }
        }
    }
}

// ---------------- per-node attention coefficients (float4, fully unrolled) ----------------
template<int H, int C>
__global__ void k_alpha(const float* __restrict__ Hf, const float* __restrict__ Asrc,
                        const float* __restrict__ Adst, float* __restrict__ AS,
                        float* __restrict__ AD, int n) {
    constexpr int HC = H * C;
    int i = blockIdx.x * blockDim.x + threadIdx.x;
    if (i >= n) return;
    float sa[H], sd[H];
    #pragma unroll
    for (int h = 0; h < H; h++) { sa[h] = 0.f; sd[h] = 0.f; }
    const float4* row = reinterpret_cast<const float4*>(Hf + (long long)i * HC);
    #pragma unroll
    for (int q = 0; q < HC / 4; q++) {
        float4 v = row[q];
        int h = (q * 4) / C;
        float4 asv = reinterpret_cast<const float4*>(Asrc)[q];
        float4 adv = reinterpret_cast<const float4*>(Adst)[q];
        sa[h] += v.x * asv.x + v.y * asv.y + v.z * asv.z + v.w * asv.w;
        sd[h] += v.x * adv.x + v.y * adv.y + v.z * adv.z + v.w * adv.w;
    }
    #pragma unroll
    for (int h = 0; h < H; h++) {
        AS[i * H + h] = sa[h];
        AD[i * H + h] = sd[h];
    }
}

// ---------------- warp-per-node ONE-PASS online softmax + aggregation ----------------
// NG = 32/(HC/4) gather groups per warp; group g handles chunk edges j = g, g+NG, ...
// Running rescale sc is warp-uniform, so per-group partial accs sum correctly at the end.
template<int H, int C, bool RELU>
__global__ void k_agg(const float* __restrict__ Hf, const float* __restrict__ AS,
                      const float* __restrict__ AD, const int* __restrict__ startA,
                      const int* __restrict__ ssrc, const float* __restrict__ bias,
                      float* __restrict__ out, int n) {
    constexpr int HC  = H * C;
    constexpr int GL  = HC / 4;                  // lanes per gather group (float4 each)
    constexpr int NG  = 32 / GL;                 // gather groups per warp
    constexpr int WPB = 8;                       // warps per block
    int warp = threadIdx.x >> 5, lane = threadIdx.x & 31;
    int nd = blockIdx.x * WPB + warp;
    if (nd >= n) return;

    __shared__ float s_w[WPB][H * 33];           // [h*33 + lane]: conflict-free
    __shared__ int   s_s[WPB][32];

    int beg = startA[nd], end = startA[nd + 1];

    float ad[H];
    loadH<H>(AD + nd * H, ad);

    int grp = lane / GL;                         // gather group
    int q   = lane % GL;                         // channel quad within row
    int myhead = (q * 4) / C;                    // per-lane constant
    float m[H], s[H], acc[4];
    #pragma unroll
    for (int h = 0; h < H; h++) { m[h] = -INFINITY; s[h] = 0.f; }
    #pragma unroll
    for (int v = 0; v < 4; v++) acc[v] = 0.f;

    for (int cbeg = beg; cbeg < end; cbeg += 32) {
        int cl = end - cbeg; if (cl > 32) cl = 32;

        float l[H];
        int src = 0;
        if (lane < cl) {
            src = ssrc[cbeg + lane];
            float as[H];
            loadH<H>(AS + src * H, as);
            #pragma unroll
            for (int h = 0; h < H; h++) l[h] = leaky(as[h] + ad[h]);
        } else {
            #pragma unroll
            for (int h = 0; h < H; h++) l[h] = -INFINITY;
        }

        // chunk max (butterfly)
        float cm[H];
        #pragma unroll
        for (int h = 0; h < H; h++) cm[h] = l[h];
        #pragma unroll
        for (int off = 16; off > 0; off >>= 1)
            #pragma unroll
            for (int h = 0; h < H; h++)
                cm[h] = fmaxf(cm[h], __shfl_xor_sync(0xffffffffu, cm[h], off));

        // merge with running max; rescale factors (m=-inf on first chunk -> exp(-inf)=0)
        float nm[H], sc[H], w[H], cs[H];
        #pragma unroll
        for (int h = 0; h < H; h++) {
            nm[h] = fmaxf(m[h], cm[h]);          // finite: cl >= 1
            sc[h] = __expf(m[h] - nm[h]);
            w[h]  = __expf(l[h] - nm[h]);        // lane >= cl: exp(-inf)=0
            cs[h] = w[h];
            m[h]  = nm[h];
        }
        // chunk exp-sum (butterfly)
        #pragma unroll
        for (int off = 16; off > 0; off >>= 1)
            #pragma unroll
            for (int h = 0; h < H; h++)
                cs[h] += __shfl_xor_sync(0xffffffffu, cs[h], off);
        #pragma unroll
        for (int h = 0; h < H; h++) s[h] = s[h] * sc[h] + cs[h];

        if (lane < cl) {
            s_s[warp][lane] = src;
            #pragma unroll
            for (int h = 0; h < H; h++) s_w[warp][h * 33 + lane] = w[h];
        }
        __syncwarp();

        {
            float rs = sc[myhead];
            #pragma unroll
            for (int v = 0; v < 4; v++) acc[v] *= rs;
            const float* base = Hf + (long long)q * 4;
            #pragma unroll 4
            for (int j = grp; j < cl; j += NG) {
                float  wj  = s_w[warp][myhead * 33 + j];
                float4 v   = *reinterpret_cast<const float4*>(base + (long long)s_s[warp][j] * HC);
                acc[0] += wj * v.x; acc[1] += wj * v.y;
                acc[2] += wj * v.z; acc[3] += wj * v.w;
            }
        }
        __syncwarp();
    }

    // sum partial accumulators across gather groups (xor on high lane bits; no-op when NG==1)
    #pragma unroll
    for (int off = GL; off < 32; off <<= 1) {
        #pragma unroll
        for (int v = 0; v < 4; v++)
            acc[v] += __shfl_xor_sync(0xffffffffu, acc[v], off);
    }

    if (lane < GL) {
        float inv = 1.f / (s[myhead] + 1e-16f);
        float4 bv = *reinterpret_cast<const float4*>(bias + lane * 4);
        float4 o;
        o.x = acc[0] * inv + bv.x;
        o.y = acc[1] * inv + bv.y;
        o.z = acc[2] * inv + bv.z;
        o.w = acc[3] * inv + bv.w;
        if (RELU) {
            o.x = fmaxf(o.x, 0.f); o.y = fmaxf(o.y, 0.f);
            o.z = fmaxf(o.z, 0.f); o.w = fmaxf(o.w, 0.f);
        }
        *reinterpret_cast<float4*>(out + (long long)nd * HC + lane * 4) = o;
    }
}

// ---------------- launcher ----------------
extern "C" void kernel_launch(void* const* d_in, const int* in_sizes, int n_in,
                              void* d_out, int out_size) {
    const float* x     = (const float*)d_in[0];
    const void*  ei    = d_in[1];
    const float* W1    = (const float*)d_in[2];
    const float* asr1  = (const float*)d_in[3];
    const float* ads1  = (const float*)d_in[4];
    const float* b1    = (const float*)d_in[5];
    const float* W2    = (const float*)d_in[6];
    const float* asr2  = (const float*)d_in[7];
    const float* ads2  = (const float*)d_in[8];
    const float* b2    = (const float*)d_in[9];
    const float* W3    = (const float*)d_in[10];
    const float* asr3  = (const float*)d_in[11];
    const float* ads3  = (const float*)d_in[12];
    const float* b3    = (const float*)d_in[13];

    int N  = in_sizes[0] / INC;
    int E  = in_sizes[1] / 2;
    int ET = E + N;

    void* p;
    cudaGetSymbolAddress(&p, g_h);      float* d_h   = (float*)p;
    cudaGetSymbolAddress(&p, g_o1);     float* d_o1  = (float*)p;
    cudaGetSymbolAddress(&p, g_o2);     float* d_o2  = (float*)p;
    cudaGetSymbolAddress(&p, g_as);     float* d_as  = (float*)p;
    cudaGetSymbolAddress(&p, g_ad);     float* d_ad  = (float*)p;
    cudaGetSymbolAddress(&p, g_startA); int*   d_st  = (int*)p;
    cudaGetSymbolAddress(&p, g_ssrc);   int*   d_ss  = (int*)p;

    // init-once side stream + fork/join events (created on the first,
    // uncaptured correctness call; same work every call thereafter)
    static cudaStream_t s1 = nullptr;
    static cudaEvent_t evFork = nullptr, evJoin = nullptr;
    if (s1 == nullptr) {
        cudaStreamCreateWithFlags(&s1, cudaStreamNonBlocking);
        cudaEventCreateWithFlags(&evFork, cudaEventDisableTiming);
        cudaEventCreateWithFlags(&evJoin, cudaEventDisableTiming);
    }

    int nb = (N + 1023) / 1024;
    int gB = (N + 127) / 128;
    int gA = (N + 7) / 8;        // 8 warps (nodes) per 256-thread block

    // ---- fork: edge preprocessing on s1, GEMM1+alpha1 on main stream ----
    cudaEventRecord(evFork, 0);
    cudaStreamWaitEvent(s1, evFork, 0);

    // s1: counting sort of edges by destination
    k_zero   <<<(N  + 255) / 256, 256, 0, s1>>>(N);
    k_detect <<<1, 32, 0, s1>>>((const int*)ei);
    k_extract<<<(ET + 255) / 256, 256, 0, s1>>>(ei, E, ET);
    k_scan1  <<<nb, 1024, 0, s1>>>(N);
    k_scan2  <<<1, 32, 0, s1>>>(nb, N);
    k_scan3  <<<nb, 1024, 0, s1>>>(N);
    k_scatter<<<(ET + 255) / 256, 256, 0, s1>>>(ET);
    cudaEventRecord(evJoin, s1);

    // main: layer-1 projection + attention coefficients (independent of edges)
    k_gemm<128, 128><<<gB, 256>>>(x, W1, d_h, N);
    k_alpha<4, 32><<<(N + 127) / 128, 128>>>(d_h, asr1, ads1, d_as, d_ad, N);

    // ---- join: aggregation needs both chains ----
    cudaStreamWaitEvent(0, evJoin, 0);

    k_agg<4, 32, true><<<gA, 256>>>(d_h, d_as, d_ad, d_st, d_ss, b1, d_o1, N);

    // layer 2: 128 -> 2 heads x 32, concat, relu
    k_gemm<128, 64><<<gB, 256>>>(d_o1, W2, d_h, N);
    k_alpha<2, 32><<<(N + 127) / 128, 128>>>(d_h, asr2, ads2, d_as, d_ad, N);
    k_agg<2, 32, true><<<gA, 256>>>(d_h, d_as, d_ad, d_st, d_ss, b2, d_o2, N);

    // layer 3: 64 -> 1 head x 16, mean (identity for 1 head), no relu
    k_gemm<64, 16><<<gB, 256>>>(d_o2, W3, d_h, N);
    k_alpha<1, 16><<<(N + 127) / 128, 128>>>(d_h, asr3, ads3, d_as, d_ad, N);
    k_agg<1, 16, false><<<gA, 256>>>(d_h, d_as, d_ad, d_st, d_ss, b3, (float*)d_out, N);
}